// round 3
// baseline (speedup 1.0000x reference)
#include <cuda_runtime.h>
#include <cuda_pipeline.h>
#include <math.h>

// ---------------------------------------------------------------------------
// CQT via collapsed kernels:
//   Stage 0: zero g_A
//   Stage 1: g_A[b][n]      = sum_k kr[b,k]*wcos[k,n] - ki[b,k]*wsin[k,n]
//            g_A[96+b][n]   = sum_k kr[b,k]*wsin[k,n] + ki[b,k]*wcos[k,n]
//   Stage 2: out[b,f] = sqrt( (sum_n x[f*512+n]*Cr[b,n])^2 +
//                             (sum_n x[f*512+n]*Ci[b,n])^2 )
// ---------------------------------------------------------------------------

#define T_SAMPLES 8388608
#define FFTLEN    2048
#define HOP       512
#define NBINS     84
#define KB        1025      // freq bins of the Fourier basis
#define NFRAMES   16381     // (T - FFTLEN)/HOP + 1
#define MROWS     192       // 96 re rows + 96 im rows (84 used each, rest zero)
#define IM_OFF    96

__device__ float g_A[MROWS * FFTLEN];   // collapsed kernels, 1.5 MB scratch

// ---------------- stage 0: zero the scratch -------------------------------
__global__ void zero_A_kernel() {
    int i = blockIdx.x * blockDim.x + threadIdx.x;   // 384*256 = 98304 float4
    ((float4*)g_A)[i] = make_float4(0.f, 0.f, 0.f, 0.f);
}

// ---------------- stage 1: collapse the two bases -------------------------
// grid (16 n-tiles, 4 bin-groups of 24, 8 k-splits), 128 threads.
// Each thread owns one n column and 24 bins; k-splits accumulate via atomics.
#define S1_BINS 24
#define S1_NT   128
__global__ __launch_bounds__(128) void s1_kernel(
    const float* __restrict__ kr, const float* __restrict__ ki,
    const float* __restrict__ wcos, const float* __restrict__ wsin)
{
    __shared__ float krs[S1_BINS][128];
    __shared__ float kis[S1_BINS][128];
    const int tid = threadIdx.x;
    const int n   = blockIdx.x * S1_NT + tid;
    const int b0  = blockIdx.y * S1_BINS;
    const int kz  = blockIdx.z;
    const int ks  = kz * 128;
    const int ke  = (kz == 7) ? KB : ks + 128;   // last split covers k=1024 too

    float accr[S1_BINS], acci[S1_BINS];
#pragma unroll
    for (int i = 0; i < S1_BINS; i++) { accr[i] = 0.f; acci[i] = 0.f; }

    for (int k0 = ks; k0 < ke; k0 += 128) {
        const int klen = min(128, ke - k0);
        __syncthreads();
        for (int t = tid; t < S1_BINS * 128; t += 128) {
            int i = t >> 7, kk = t & 127;
            int b = b0 + i;
            bool ok = (kk < klen) && (b < NBINS);
            krs[i][kk] = ok ? kr[b * KB + k0 + kk] : 0.f;
            kis[i][kk] = ok ? ki[b * KB + k0 + kk] : 0.f;
        }
        __syncthreads();
#pragma unroll 4
        for (int kk = 0; kk < klen; kk++) {
            float wc = wcos[(size_t)(k0 + kk) * FFTLEN + n];
            float ws = wsin[(size_t)(k0 + kk) * FFTLEN + n];
#pragma unroll
            for (int i = 0; i < S1_BINS; i++) {
                float a = krs[i][kk], c = kis[i][kk];
                accr[i] = fmaf(a,  wc, accr[i]);
                accr[i] = fmaf(-c, ws, accr[i]);
                acci[i] = fmaf(a,  ws, acci[i]);
                acci[i] = fmaf(c,  wc, acci[i]);
            }
        }
    }
#pragma unroll
    for (int i = 0; i < S1_BINS; i++) {
        int b = b0 + i;
        if (b < NBINS) {
            atomicAdd(&g_A[(size_t)b * FFTLEN + n], accr[i]);
            atomicAdd(&g_A[(size_t)(IM_OFF + b) * FFTLEN + n], acci[i]);
        }
    }
}

// ---------------- stage 2: main GEMM + magnitude epilogue -----------------
// Block tile: 192 rows (96 re + 96 im) x 64 frames. 192 threads.
// Thread micro-tile: 4 re rows + their 4 im rows x 8 frames = 64 accums,
// so sqrt(re^2+im^2) is computed thread-locally.
// K is tiled by 16, cp.async double-buffered, XOR-swizzled smem
// (row stride 16 words == 0 mod 32 would otherwise serialize LDS banks).
#define KT 16
#define NT 64
__global__ __launch_bounds__(192, 2) void s2_kernel(
    const float* __restrict__ x, float* __restrict__ out)
{
    __shared__ float As[2][MROWS * KT];   // 2 * 12 KB
    __shared__ float Bs[2][NT * KT];      // 2 * 4 KB
    const int tid = threadIdx.x;
    const int g   = tid >> 3;   // 0..23 -> bin rows 4g..4g+3 (+96 for imag)
    const int fg  = tid & 7;    // 0..7  -> frames 8fg..8fg+7
    const int f0  = blockIdx.x * NT;

    float accr[4][8], acci[4][8];
#pragma unroll
    for (int i = 0; i < 4; i++)
#pragma unroll
        for (int j = 0; j < 8; j++) { accr[i][j] = 0.f; acci[i][j] = 0.f; }

    auto load_tiles = [&](int buf, int k0) {
        // A: row m = tid, 4 x 16B chunks, chunk index XORed with (m>>2)&3
        {
            const float* src = g_A + (size_t)tid * FFTLEN + k0;
            float* drow = &As[buf][tid * KT];
            const int key = (tid >> 2) & 3;
#pragma unroll
            for (int c = 0; c < 4; c++)
                __pipeline_memcpy_async(drow + ((c ^ key) << 2), src + (c << 2), 16);
        }
        // B: 64 frame-rows x 4 chunks = 256 tasks; frames beyond NFRAMES zero-fill
        for (int t = tid; t < NT * 4; t += 192) {
            int fr = t >> 2, c = t & 3;
            int f  = f0 + fr;
            const int key = (fr >> 3) & 3;
            float* dst = &Bs[buf][fr * KT + ((c ^ key) << 2)];
            const float* src = x + (size_t)f * HOP + k0 + (c << 2);
            __pipeline_memcpy_async(dst, src, 16, (f < NFRAMES) ? 0u : 16u);
        }
    };

    load_tiles(0, 0);
    __pipeline_commit();

    int buf = 0;
    const int NKT = FFTLEN / KT;   // 128 k-tiles
    for (int kt = 0; kt < NKT; kt++) {
        if (kt + 1 < NKT) {
            load_tiles(buf ^ 1, (kt + 1) * KT);
            __pipeline_commit();
            __pipeline_wait_prior(1);
        } else {
            __pipeline_wait_prior(0);
        }
        __syncthreads();

        const float* A0 = &As[buf][0];
        const float* B0 = &Bs[buf][0];
#pragma unroll 4
        for (int k = 0; k < KT; k++) {
            const int kc = k >> 2, kq = k & 3;
            const int swa = ((kc ^ (g  & 3)) << 2) + kq;
            const int swb = ((kc ^ (fg & 3)) << 2) + kq;
            float ar[4], ai[4], bb[8];
#pragma unroll
            for (int i = 0; i < 4; i++) {
                ar[i] = A0[(4 * g + i) * KT + swa];
                ai[i] = A0[(IM_OFF + 4 * g + i) * KT + swa];
            }
#pragma unroll
            for (int j = 0; j < 8; j++)
                bb[j] = B0[(8 * fg + j) * KT + swb];
#pragma unroll
            for (int i = 0; i < 4; i++)
#pragma unroll
                for (int j = 0; j < 8; j++) {
                    accr[i][j] = fmaf(ar[i], bb[j], accr[i][j]);
                    acci[i][j] = fmaf(ai[i], bb[j], acci[i][j]);
                }
        }
        __syncthreads();
        buf ^= 1;
    }

    // epilogue: magnitude, guarded stores (bins 84..95 and frames >= NFRAMES pad)
#pragma unroll
    for (int i = 0; i < 4; i++) {
        int b = 4 * g + i;
        if (b < NBINS) {
#pragma unroll
            for (int j = 0; j < 8; j++) {
                int f = f0 + 8 * fg + j;
                if (f < NFRAMES)
                    out[(size_t)b * NFRAMES + f] =
                        sqrtf(accr[i][j] * accr[i][j] + acci[i][j] * acci[i][j]);
            }
        }
    }
}

// ---------------------------------------------------------------------------
extern "C" void kernel_launch(void* const* d_in, const int* in_sizes, int n_in,
                              void* d_out, int out_size)
{
    const float* x    = (const float*)d_in[0];
    const float* wcos = (const float*)d_in[1];
    const float* wsin = (const float*)d_in[2];
    const float* kr   = (const float*)d_in[3];
    const float* ki   = (const float*)d_in[4];
    float* out = (float*)d_out;

    zero_A_kernel<<<(MROWS * FFTLEN / 4) / 256, 256>>>();
    s1_kernel<<<dim3(FFTLEN / S1_NT, 4, 8), 128>>>(kr, ki, wcos, wsin);
    s2_kernel<<<(NFRAMES + NT - 1) / NT, 192>>>(x, out);
}

// round 6
// speedup vs baseline: 2.5306x; 2.5306x over previous
#include <cuda_runtime.h>
#include <cuda_pipeline.h>
#include <cuda_bf16.h>
#include <math.h>
#include <stdint.h>

// ---------------------------------------------------------------------------
// CQT via collapsed kernels + mma.sync bf16 (2-way split) main GEMM.
//   Stage 0: zero g_A
//   Stage 1: g_A[b][n]    = sum_k kr[b,k]*wcos[k,n] - ki[b,k]*wsin[k,n]   (re)
//            g_A[96+b][n] = sum_k kr[b,k]*wsin[k,n] + ki[b,k]*wcos[k,n]   (im)
//   Stage 1b: split g_A -> g_Bh + g_Bl (bf16 hi/lo)
//   Stage 2: mma.sync GEMM  D[frames, 192 bins] over K=2048:
//            D = Xh*Bh + Xh*Bl + Xl*Bh   (x split to bf16 hi/lo on the fly)
//            out[b,f] = sqrt(D[f,b]^2 + D[f,96+b]^2)
// ---------------------------------------------------------------------------

#define FFTLEN    2048
#define HOP       512
#define NBINS     84
#define KB        1025
#define NFRAMES   16381
#define NB_PAD    192       // 96 re rows + 96 im rows (84 used each, rest zero)
#define IM_OFF    96

__device__ float         g_A [NB_PAD * FFTLEN];
__device__ __nv_bfloat16 g_Bh[NB_PAD * FFTLEN];
__device__ __nv_bfloat16 g_Bl[NB_PAD * FFTLEN];

// ---------------- helpers ---------------------------------------------------
__device__ __forceinline__ uint32_t smem_u32(const void* p) {
    uint32_t a;
    asm("{ .reg .u64 t; cvta.to.shared.u64 t, %1; cvt.u32.u64 %0, t; }"
        : "=r"(a) : "l"(p));
    return a;
}
__device__ __forceinline__ void ldmx4(uint32_t* r, uint32_t addr) {
    asm volatile("ldmatrix.sync.aligned.m8n8.x4.shared.b16 {%0,%1,%2,%3}, [%4];"
                 : "=r"(r[0]), "=r"(r[1]), "=r"(r[2]), "=r"(r[3]) : "r"(addr));
}
__device__ __forceinline__ void mma16816(float* d, const uint32_t* a,
                                         uint32_t b0, uint32_t b1) {
    asm volatile(
        "mma.sync.aligned.m16n8k16.row.col.f32.bf16.bf16.f32 "
        "{%0,%1,%2,%3}, {%4,%5,%6,%7}, {%8,%9}, {%0,%1,%2,%3};"
        : "+f"(d[0]), "+f"(d[1]), "+f"(d[2]), "+f"(d[3])
        : "r"(a[0]), "r"(a[1]), "r"(a[2]), "r"(a[3]), "r"(b0), "r"(b1));
}
// SW128-style swizzle on byte offsets (row stride 128B)
#define SW(o) ((o) ^ (((o) >> 3) & 0x70))

// ---------------- stage 0: zero the scratch -------------------------------
__global__ void zero_A_kernel() {
    int i = blockIdx.x * blockDim.x + threadIdx.x;   // 384*256 = 98304 float4
    ((float4*)g_A)[i] = make_float4(0.f, 0.f, 0.f, 0.f);
}

// ---------------- stage 1: collapse the two bases (fp32 scalar) ------------
#define S1_BINS 24
#define S1_NT   128
__global__ __launch_bounds__(128) void s1_kernel(
    const float* __restrict__ kr, const float* __restrict__ ki,
    const float* __restrict__ wcos, const float* __restrict__ wsin)
{
    __shared__ float krs[S1_BINS][128];
    __shared__ float kis[S1_BINS][128];
    const int tid = threadIdx.x;
    const int n   = blockIdx.x * S1_NT + tid;
    const int b0  = blockIdx.y * S1_BINS;
    const int kz  = blockIdx.z;
    const int ks  = kz * 128;
    const int ke  = (kz == 7) ? KB : ks + 128;

    float accr[S1_BINS], acci[S1_BINS];
#pragma unroll
    for (int i = 0; i < S1_BINS; i++) { accr[i] = 0.f; acci[i] = 0.f; }

    for (int k0 = ks; k0 < ke; k0 += 128) {
        const int klen = min(128, ke - k0);
        __syncthreads();
        for (int t = tid; t < S1_BINS * 128; t += 128) {
            int i = t >> 7, kk = t & 127;
            int b = b0 + i;
            bool ok = (kk < klen) && (b < NBINS);
            krs[i][kk] = ok ? kr[b * KB + k0 + kk] : 0.f;
            kis[i][kk] = ok ? ki[b * KB + k0 + kk] : 0.f;
        }
        __syncthreads();
#pragma unroll 4
        for (int kk = 0; kk < klen; kk++) {
            float wc = wcos[(size_t)(k0 + kk) * FFTLEN + n];
            float ws = wsin[(size_t)(k0 + kk) * FFTLEN + n];
#pragma unroll
            for (int i = 0; i < S1_BINS; i++) {
                float a = krs[i][kk], c = kis[i][kk];
                accr[i] = fmaf(a,  wc, accr[i]);
                accr[i] = fmaf(-c, ws, accr[i]);
                acci[i] = fmaf(a,  ws, acci[i]);
                acci[i] = fmaf(c,  wc, acci[i]);
            }
        }
    }
#pragma unroll
    for (int i = 0; i < S1_BINS; i++) {
        int b = b0 + i;
        if (b < NBINS) {
            atomicAdd(&g_A[(size_t)b * FFTLEN + n], accr[i]);
            atomicAdd(&g_A[(size_t)(IM_OFF + b) * FFTLEN + n], acci[i]);
        }
    }
}

// ---------------- stage 1b: fp32 -> bf16 hi/lo split -----------------------
__device__ __forceinline__ uint32_t pk(__nv_bfloat16 a, __nv_bfloat16 b) {
    __nv_bfloat162 t(a, b);
    return *(uint32_t*)&t;
}
__global__ void bsplit_kernel() {
    int i = blockIdx.x * blockDim.x + threadIdx.x;   // per float4, 98304 total
    float4 v = ((const float4*)g_A)[i];
    __nv_bfloat16 h0 = __float2bfloat16_rn(v.x), h1 = __float2bfloat16_rn(v.y);
    __nv_bfloat16 h2 = __float2bfloat16_rn(v.z), h3 = __float2bfloat16_rn(v.w);
    __nv_bfloat16 l0 = __float2bfloat16_rn(v.x - __bfloat162float(h0));
    __nv_bfloat16 l1 = __float2bfloat16_rn(v.y - __bfloat162float(h1));
    __nv_bfloat16 l2 = __float2bfloat16_rn(v.z - __bfloat162float(h2));
    __nv_bfloat16 l3 = __float2bfloat16_rn(v.w - __bfloat162float(h3));
    ((uint2*)g_Bh)[i] = make_uint2(pk(h0, h1), pk(h2, h3));
    ((uint2*)g_Bl)[i] = make_uint2(pk(l0, l1), pk(l2, l3));
}

// ---------------- stage 2: mma.sync GEMM + magnitude epilogue --------------
// Per CTA: D[128 frames, 192 bins], K=2048 in chunks of 64 bf16, double
// buffered. 8 warps: 4 M-groups (32 frames) x 2 N-groups (48 re + 48 im bins).
// 3 passes: Xh*Bh, Xh*Bl, Xl*Bh. Accumulators hold re and im of the same bin
// in the same thread/slot, so the sqrt epilogue is thread-local.
//
// Stage SMEM layout (80 KB): Ah 16K | Al 16K | Bh 24K | Bl 24K
#define S2_STAGE_BYTES 81920
#define S2_SMEM_TOTAL  (2 * S2_STAGE_BYTES)
#define KC 64                      // bf16 per K chunk (128 B rows)
#define NCHUNK (FFTLEN / KC)       // 32

__global__ __launch_bounds__(256, 1) void s2_mma_kernel(
    const float* __restrict__ x, float* __restrict__ out)
{
    extern __shared__ __align__(1024) char smem[];
    const uint32_t smem_base = smem_u32(smem);
    const int tid = threadIdx.x;
    const int wid = tid >> 5;
    const int lid = tid & 31;
    const int wm  = wid & 3;        // M group: frames 32*wm..+31
    const int wn  = wid >> 2;       // N group: re bins 48*wn..+47 (+im twins)
    const int f0  = blockIdx.x * 128;

    // ---- per-thread ldmatrix address components ----
    const int i8 = lid & 7, g = lid >> 3;
    // A tiles: reg order (rows0-7 klo, rows8-15 klo, rows0-7 khi, rows8-15 khi)
    uint32_t arow128[2], akey[2];
#pragma unroll
    for (int mt = 0; mt < 2; mt++) {
        int r = 32 * wm + 16 * mt + ((g & 1) << 3) + i8;
        arow128[mt] = r << 7;
        akey[mt]    = (r & 7) << 4;
    }
    const uint32_t acolg = (g >> 1) << 4;
    // B tiles: reg order (n0-7 klo, n0-7 khi, n8-15 klo, n8-15 khi)
    uint32_t brow128[6], bkey[6];
#pragma unroll
    for (int p = 0; p < 6; p++) {
        int n0 = (p < 3) ? (48 * wn + 16 * p) : (IM_OFF + 48 * wn + 16 * (p - 3));
        int r  = n0 + ((g >> 1) << 3) + i8;
        brow128[p] = r << 7;
        bkey[p]    = (r & 7) << 4;
    }
    const uint32_t bcolg = (g & 1) << 4;

    float acc[2][12][4];
#pragma unroll
    for (int m = 0; m < 2; m++)
#pragma unroll
        for (int n = 0; n < 12; n++)
#pragma unroll
            for (int q = 0; q < 4; q++) acc[m][n][q] = 0.f;

    auto load_tiles = [&](int buf, int k0) {
        char* st = smem + buf * S2_STAGE_BYTES;
        // B tiles (bins, bf16 hi+lo): 192 rows x 128B each, via cp.async
        for (int t = tid; t < NB_PAD * 8 * 2; t += 256) {
            int arr = t / (NB_PAD * 8);
            int rem = t - arr * (NB_PAD * 8);
            int r = rem >> 3, ch = rem & 7;
            const __nv_bfloat16* src =
                (arr ? g_Bl : g_Bh) + (size_t)r * FFTLEN + k0 + ch * 8;
            char* dst = st + 32768 + arr * 24576 + SW(r * 128 + ch * 16);
            __pipeline_memcpy_async(dst, src, 16);
        }
        // A tiles (frames): LDG x fp32, split to bf16 hi/lo, swizzled STS
        for (int t = tid; t < 128 * 16; t += 256) {
            int m = t >> 4, ch = t & 15;
            int f = f0 + m;
            float4 v = make_float4(0.f, 0.f, 0.f, 0.f);
            if (f < NFRAMES)
                v = *(const float4*)(x + (size_t)f * HOP + k0 + ch * 4);
            __nv_bfloat16 h0 = __float2bfloat16_rn(v.x), h1 = __float2bfloat16_rn(v.y);
            __nv_bfloat16 h2 = __float2bfloat16_rn(v.z), h3 = __float2bfloat16_rn(v.w);
            __nv_bfloat16 l0 = __float2bfloat16_rn(v.x - __bfloat162float(h0));
            __nv_bfloat16 l1 = __float2bfloat16_rn(v.y - __bfloat162float(h1));
            __nv_bfloat16 l2 = __float2bfloat16_rn(v.z - __bfloat162float(h2));
            __nv_bfloat16 l3 = __float2bfloat16_rn(v.w - __bfloat162float(h3));
            int off = SW(m * 128 + ch * 8);
            *(uint2*)(st + off)         = make_uint2(pk(h0, h1), pk(h2, h3));
            *(uint2*)(st + 16384 + off) = make_uint2(pk(l0, l1), pk(l2, l3));
        }
    };

    load_tiles(0, 0);
    __pipeline_commit();

#pragma unroll 1
    for (int c = 0; c < NCHUNK; c++) {
        const int buf = c & 1;
        if (c + 1 < NCHUNK) {
            load_tiles(buf ^ 1, (c + 1) * KC);
            __pipeline_commit();
            __pipeline_wait_prior(1);
        } else {
            __pipeline_wait_prior(0);
        }
        __syncthreads();   // tiles for chunk c visible (cp.async + STS)

        const uint32_t sbase = smem_base + buf * S2_STAGE_BYTES;
#pragma unroll 1
        for (int pass = 0; pass < 3; pass++) {
            const uint32_t Ab = sbase + (pass == 2 ? 16384 : 0);
            const uint32_t Bb = sbase + 32768 + (pass == 1 ? 24576 : 0);
#pragma unroll
            for (int ks = 0; ks < 4; ks++) {
                const uint32_t kc32 = ks * 32;
                uint32_t a[2][4];
#pragma unroll
                for (int mt = 0; mt < 2; mt++)
                    ldmx4(a[mt], Ab + arow128[mt] + ((kc32 + acolg) ^ akey[mt]));
                uint32_t bf[6][4];
#pragma unroll
                for (int p = 0; p < 6; p++)
                    ldmx4(bf[p], Bb + brow128[p] + ((kc32 + bcolg) ^ bkey[p]));
#pragma unroll
                for (int mt = 0; mt < 2; mt++)
#pragma unroll
                    for (int p = 0; p < 6; p++) {
                        const int j = (p < 3) ? 2 * p : 6 + 2 * (p - 3);
                        mma16816(acc[mt][j],     a[mt], bf[p][0], bf[p][1]);
                        mma16816(acc[mt][j + 1], a[mt], bf[p][2], bf[p][3]);
                    }
            }
        }
        __syncthreads();   // all warps done with buf c before it is refilled
    }

    // epilogue: thread-local magnitude, guarded scattered stores
#pragma unroll
    for (int mt = 0; mt < 2; mt++)
#pragma unroll
        for (int j = 0; j < 6; j++)
#pragma unroll
            for (int q = 0; q < 4; q++) {
                int f = f0 + 32 * wm + 16 * mt + (lid >> 2) + ((q & 2) ? 8 : 0);
                int b = 48 * wn + 8 * j + ((lid & 3) << 1) + (q & 1);
                if (b < NBINS && f < NFRAMES) {
                    float re = acc[mt][j][q], im = acc[mt][j + 6][q];
                    out[(size_t)b * NFRAMES + f] = sqrtf(re * re + im * im);
                }
            }
}

// ---------------------------------------------------------------------------
extern "C" void kernel_launch(void* const* d_in, const int* in_sizes, int n_in,
                              void* d_out, int out_size)
{
    const float* x    = (const float*)d_in[0];
    const float* wcos = (const float*)d_in[1];
    const float* wsin = (const float*)d_in[2];
    const float* kr   = (const float*)d_in[3];
    const float* ki   = (const float*)d_in[4];
    float* out = (float*)d_out;

    cudaFuncSetAttribute(s2_mma_kernel,
                         cudaFuncAttributeMaxDynamicSharedMemorySize, S2_SMEM_TOTAL);

    zero_A_kernel<<<(NB_PAD * FFTLEN / 4) / 256, 256>>>();
    s1_kernel<<<dim3(FFTLEN / S1_NT, 4, 8), 128>>>(kr, ki, wcos, wsin);
    bsplit_kernel<<<(NB_PAD * FFTLEN / 4) / 256, 256>>>();
    s2_mma_kernel<<<(NFRAMES + 127) / 128, 256, S2_SMEM_TOTAL>>>(x, out);
}

// round 7
// speedup vs baseline: 2.5577x; 1.0107x over previous
#include <cuda_runtime.h>
#include <cuda_pipeline.h>
#include <cuda_bf16.h>
#include <math.h>
#include <stdint.h>

// ---------------------------------------------------------------------------
// CQT via collapsed kernels + mma.sync bf16 (2-way split) main GEMM.
//   Stage 0: zero g_A
//   Stage 1: g_A[b][n]    = sum_k kr[b,k]*wcos[k,n] - ki[b,k]*wsin[k,n]   (re)
//            g_A[96+b][n] = sum_k kr[b,k]*wsin[k,n] + ki[b,k]*wcos[k,n]   (im)
//   Stage 1b: split g_A -> g_Bh + g_Bl (bf16 hi/lo)
//   Stage 2: mma.sync GEMM  D[frames, 192 bins] over K=2048:
//            D = Xh*Bh + Xh*Bl + Xl*Bh   (x split to bf16 hi/lo on the fly)
//            out[b,f] = sqrt(D[f,b]^2 + D[f,96+b]^2)
// ---------------------------------------------------------------------------

#define FFTLEN    2048
#define HOP       512
#define NBINS     84
#define KB        1025
#define NFRAMES   16381
#define NB_PAD    192       // 96 re rows + 96 im rows (84 used each, rest zero)
#define IM_OFF    96

__device__ float         g_A [NB_PAD * FFTLEN];
__device__ __nv_bfloat16 g_Bh[NB_PAD * FFTLEN];
__device__ __nv_bfloat16 g_Bl[NB_PAD * FFTLEN];

// ---------------- helpers ---------------------------------------------------
__device__ __forceinline__ uint32_t smem_u32(const void* p) {
    uint32_t a;
    asm("{ .reg .u64 t; cvta.to.shared.u64 t, %1; cvt.u32.u64 %0, t; }"
        : "=r"(a) : "l"(p));
    return a;
}
__device__ __forceinline__ void ldmx4(uint32_t* r, uint32_t addr) {
    asm volatile("ldmatrix.sync.aligned.m8n8.x4.shared.b16 {%0,%1,%2,%3}, [%4];"
                 : "=r"(r[0]), "=r"(r[1]), "=r"(r[2]), "=r"(r[3]) : "r"(addr));
}
__device__ __forceinline__ void mma16816(float* d, const uint32_t* a,
                                         uint32_t b0, uint32_t b1) {
    asm volatile(
        "mma.sync.aligned.m16n8k16.row.col.f32.bf16.bf16.f32 "
        "{%0,%1,%2,%3}, {%4,%5,%6,%7}, {%8,%9}, {%0,%1,%2,%3};"
        : "+f"(d[0]), "+f"(d[1]), "+f"(d[2]), "+f"(d[3])
        : "r"(a[0]), "r"(a[1]), "r"(a[2]), "r"(a[3]), "r"(b0), "r"(b1));
}
// SW128-style swizzle on byte offsets (row stride 128B)
#define SW(o) ((o) ^ (((o) >> 3) & 0x70))

// ---------------- stage 0: zero the scratch -------------------------------
__global__ void zero_A_kernel() {
    int i = blockIdx.x * blockDim.x + threadIdx.x;   // 384*256 = 98304 float4
    ((float4*)g_A)[i] = make_float4(0.f, 0.f, 0.f, 0.f);
}

// ---------------- stage 1: collapse the two bases (fp32 scalar) ------------
#define S1_BINS 24
#define S1_NT   128
__global__ __launch_bounds__(128) void s1_kernel(
    const float* __restrict__ kr, const float* __restrict__ ki,
    const float* __restrict__ wcos, const float* __restrict__ wsin)
{
    __shared__ float krs[S1_BINS][128];
    __shared__ float kis[S1_BINS][128];
    const int tid = threadIdx.x;
    const int n   = blockIdx.x * S1_NT + tid;
    const int b0  = blockIdx.y * S1_BINS;
    const int kz  = blockIdx.z;
    const int ks  = kz * 128;
    const int ke  = (kz == 7) ? KB : ks + 128;

    float accr[S1_BINS], acci[S1_BINS];
#pragma unroll
    for (int i = 0; i < S1_BINS; i++) { accr[i] = 0.f; acci[i] = 0.f; }

    for (int k0 = ks; k0 < ke; k0 += 128) {
        const int klen = min(128, ke - k0);
        __syncthreads();
        for (int t = tid; t < S1_BINS * 128; t += 128) {
            int i = t >> 7, kk = t & 127;
            int b = b0 + i;
            bool ok = (kk < klen) && (b < NBINS);
            krs[i][kk] = ok ? kr[b * KB + k0 + kk] : 0.f;
            kis[i][kk] = ok ? ki[b * KB + k0 + kk] : 0.f;
        }
        __syncthreads();
#pragma unroll 4
        for (int kk = 0; kk < klen; kk++) {
            float wc = wcos[(size_t)(k0 + kk) * FFTLEN + n];
            float ws = wsin[(size_t)(k0 + kk) * FFTLEN + n];
#pragma unroll
            for (int i = 0; i < S1_BINS; i++) {
                float a = krs[i][kk], c = kis[i][kk];
                accr[i] = fmaf(a,  wc, accr[i]);
                accr[i] = fmaf(-c, ws, accr[i]);
                acci[i] = fmaf(a,  ws, acci[i]);
                acci[i] = fmaf(c,  wc, acci[i]);
            }
        }
    }
#pragma unroll
    for (int i = 0; i < S1_BINS; i++) {
        int b = b0 + i;
        if (b < NBINS) {
            atomicAdd(&g_A[(size_t)b * FFTLEN + n], accr[i]);
            atomicAdd(&g_A[(size_t)(IM_OFF + b) * FFTLEN + n], acci[i]);
        }
    }
}

// ---------------- stage 1b: fp32 -> bf16 hi/lo split -----------------------
__device__ __forceinline__ uint32_t pk(__nv_bfloat16 a, __nv_bfloat16 b) {
    __nv_bfloat162 t(a, b);
    return *(uint32_t*)&t;
}
__global__ void bsplit_kernel() {
    int i = blockIdx.x * blockDim.x + threadIdx.x;   // per float4, 98304 total
    float4 v = ((const float4*)g_A)[i];
    __nv_bfloat16 h0 = __float2bfloat16_rn(v.x), h1 = __float2bfloat16_rn(v.y);
    __nv_bfloat16 h2 = __float2bfloat16_rn(v.z), h3 = __float2bfloat16_rn(v.w);
    __nv_bfloat16 l0 = __float2bfloat16_rn(v.x - __bfloat162float(h0));
    __nv_bfloat16 l1 = __float2bfloat16_rn(v.y - __bfloat162float(h1));
    __nv_bfloat16 l2 = __float2bfloat16_rn(v.z - __bfloat162float(h2));
    __nv_bfloat16 l3 = __float2bfloat16_rn(v.w - __bfloat162float(h3));
    ((uint2*)g_Bh)[i] = make_uint2(pk(h0, h1), pk(h2, h3));
    ((uint2*)g_Bl)[i] = make_uint2(pk(l0, l1), pk(l2, l3));
}

// ---------------- stage 2: mma.sync GEMM + magnitude epilogue --------------
// Per CTA: D[128 frames, 192 bins], K=2048 in chunks of 64 bf16, double
// buffered. 8 warps: 4 M-groups (32 frames) x 2 N-groups (48 re + 48 im bins).
// 3 passes: Xh*Bh, Xh*Bl, Xl*Bh. Accumulators hold re and im of the same bin
// in the same thread/slot, so the sqrt epilogue is thread-local.
//
// Stage SMEM layout (80 KB): Ah 16K | Al 16K | Bh 24K | Bl 24K
#define S2_STAGE_BYTES 81920
#define S2_SMEM_TOTAL  (2 * S2_STAGE_BYTES)
#define KC 64                      // bf16 per K chunk (128 B rows)
#define NCHUNK (FFTLEN / KC)       // 32

__global__ __launch_bounds__(256, 1) void s2_mma_kernel(
    const float* __restrict__ x, float* __restrict__ out)
{
    extern __shared__ __align__(1024) char smem[];
    const uint32_t smem_base = smem_u32(smem);
    const int tid = threadIdx.x;
    const int wid = tid >> 5;
    const int lid = tid & 31;
    const int wm  = wid & 3;        // M group: frames 32*wm..+31
    const int wn  = wid >> 2;       // N group: re bins 48*wn..+47 (+im twins)
    const int f0  = blockIdx.x * 128;

    // ---- per-thread ldmatrix address components ----
    const int i8 = lid & 7, g = lid >> 3;
    // A tiles: reg order (rows0-7 klo, rows8-15 klo, rows0-7 khi, rows8-15 khi)
    uint32_t arow128[2], akey[2];
#pragma unroll
    for (int mt = 0; mt < 2; mt++) {
        int r = 32 * wm + 16 * mt + ((g & 1) << 3) + i8;
        arow128[mt] = r << 7;
        akey[mt]    = (r & 7) << 4;
    }
    const uint32_t acolg = (g >> 1) << 4;
    // B tiles: reg order (n0-7 klo, n0-7 khi, n8-15 klo, n8-15 khi)
    uint32_t brow128[6], bkey[6];
#pragma unroll
    for (int p = 0; p < 6; p++) {
        int n0 = (p < 3) ? (48 * wn + 16 * p) : (IM_OFF + 48 * wn + 16 * (p - 3));
        int r  = n0 + ((g >> 1) << 3) + i8;
        brow128[p] = r << 7;
        bkey[p]    = (r & 7) << 4;
    }
    const uint32_t bcolg = (g & 1) << 4;

    float acc[2][12][4];
#pragma unroll
    for (int m = 0; m < 2; m++)
#pragma unroll
        for (int n = 0; n < 12; n++)
#pragma unroll
            for (int q = 0; q < 4; q++) acc[m][n][q] = 0.f;

    auto load_tiles = [&](int buf, int k0) {
        char* st = smem + buf * S2_STAGE_BYTES;
        // B tiles (bins, bf16 hi+lo): 192 rows x 128B each, via cp.async
        for (int t = tid; t < NB_PAD * 8 * 2; t += 256) {
            int arr = t / (NB_PAD * 8);
            int rem = t - arr * (NB_PAD * 8);
            int r = rem >> 3, ch = rem & 7;
            const __nv_bfloat16* src =
                (arr ? g_Bl : g_Bh) + (size_t)r * FFTLEN + k0 + ch * 8;
            char* dst = st + 32768 + arr * 24576 + SW(r * 128 + ch * 16);
            __pipeline_memcpy_async(dst, src, 16);
        }
        // A tiles (frames): LDG x fp32, split to bf16 hi/lo, swizzled STS
        for (int t = tid; t < 128 * 16; t += 256) {
            int m = t >> 4, ch = t & 15;
            int f = f0 + m;
            float4 v = make_float4(0.f, 0.f, 0.f, 0.f);
            if (f < NFRAMES)
                v = *(const float4*)(x + (size_t)f * HOP + k0 + ch * 4);
            __nv_bfloat16 h0 = __float2bfloat16_rn(v.x), h1 = __float2bfloat16_rn(v.y);
            __nv_bfloat16 h2 = __float2bfloat16_rn(v.z), h3 = __float2bfloat16_rn(v.w);
            __nv_bfloat16 l0 = __float2bfloat16_rn(v.x - __bfloat162float(h0));
            __nv_bfloat16 l1 = __float2bfloat16_rn(v.y - __bfloat162float(h1));
            __nv_bfloat16 l2 = __float2bfloat16_rn(v.z - __bfloat162float(h2));
            __nv_bfloat16 l3 = __float2bfloat16_rn(v.w - __bfloat162float(h3));
            int off = SW(m * 128 + ch * 8);
            *(uint2*)(st + off)         = make_uint2(pk(h0, h1), pk(h2, h3));
            *(uint2*)(st + 16384 + off) = make_uint2(pk(l0, l1), pk(l2, l3));
        }
    };

    load_tiles(0, 0);
    __pipeline_commit();

#pragma unroll 1
    for (int c = 0; c < NCHUNK; c++) {
        const int buf = c & 1;
        if (c + 1 < NCHUNK) {
            load_tiles(buf ^ 1, (c + 1) * KC);
            __pipeline_commit();
            __pipeline_wait_prior(1);
        } else {
            __pipeline_wait_prior(0);
        }
        __syncthreads();   // tiles for chunk c visible (cp.async + STS)

        const uint32_t sbase = smem_base + buf * S2_STAGE_BYTES;
#pragma unroll 1
        for (int pass = 0; pass < 3; pass++) {
            const uint32_t Ab = sbase + (pass == 2 ? 16384 : 0);
            const uint32_t Bb = sbase + 32768 + (pass == 1 ? 24576 : 0);
#pragma unroll
            for (int ks = 0; ks < 4; ks++) {
                const uint32_t kc32 = ks * 32;
                uint32_t a[2][4];
#pragma unroll
                for (int mt = 0; mt < 2; mt++)
                    ldmx4(a[mt], Ab + arow128[mt] + ((kc32 + acolg) ^ akey[mt]));
                uint32_t bf[6][4];
#pragma unroll
                for (int p = 0; p < 6; p++)
                    ldmx4(bf[p], Bb + brow128[p] + ((kc32 + bcolg) ^ bkey[p]));
#pragma unroll
                for (int mt = 0; mt < 2; mt++)
#pragma unroll
                    for (int p = 0; p < 6; p++) {
                        const int j = (p < 3) ? 2 * p : 6 + 2 * (p - 3);
                        mma16816(acc[mt][j],     a[mt], bf[p][0], bf[p][1]);
                        mma16816(acc[mt][j + 1], a[mt], bf[p][2], bf[p][3]);
                    }
            }
        }
        __syncthreads();   // all warps done with buf c before it is refilled
    }

    // epilogue: thread-local magnitude, guarded scattered stores
#pragma unroll
    for (int mt = 0; mt < 2; mt++)
#pragma unroll
        for (int j = 0; j < 6; j++)
#pragma unroll
            for (int q = 0; q < 4; q++) {
                int f = f0 + 32 * wm + 16 * mt + (lid >> 2) + ((q & 2) ? 8 : 0);
                int b = 48 * wn + 8 * j + ((lid & 3) << 1) + (q & 1);
                if (b < NBINS && f < NFRAMES) {
                    float re = acc[mt][j][q], im = acc[mt][j + 6][q];
                    out[(size_t)b * NFRAMES + f] = sqrtf(re * re + im * im);
                }
            }
}

// ---------------------------------------------------------------------------
extern "C" void kernel_launch(void* const* d_in, const int* in_sizes, int n_in,
                              void* d_out, int out_size)
{
    const float* x    = (const float*)d_in[0];
    const float* wcos = (const float*)d_in[1];
    const float* wsin = (const float*)d_in[2];
    const float* kr   = (const float*)d_in[3];
    const float* ki   = (const float*)d_in[4];
    float* out = (float*)d_out;

    cudaFuncSetAttribute(s2_mma_kernel,
                         cudaFuncAttributeMaxDynamicSharedMemorySize, S2_SMEM_TOTAL);

    zero_A_kernel<<<(NB_PAD * FFTLEN / 4) / 256, 256>>>();
    s1_kernel<<<dim3(FFTLEN / S1_NT, 4, 8), 128>>>(kr, ki, wcos, wsin);
    bsplit_kernel<<<(NB_PAD * FFTLEN / 4) / 256, 256>>>();
    s2_mma_kernel<<<(NFRAMES + 127) / 128, 256, S2_SMEM_TOTAL>>>(x, out);
}